// round 7
// baseline (speedup 1.0000x reference)
#include <cuda_runtime.h>

// VisibilityHeatmap: per (b,k) keypoint, NDC coord -> pixel index, gather ONE
// heatmap value, threshold, broadcast mask to both coord lanes.
//
// coords [B=32,K=64,2] f32, heatmaps [B,K,256,256] f32, out [B,K,2] f32.
// Latency-bound micro-kernel: 2048 independent gathers, ~260KB touched.
//
// Evidence so far (ncu kernel dur / harness wall):
//   branchy body, grid 8x256 : 7.7-8.2us / 4.6us (fast-clock regime)
//   branchless,  grid 64x32  : 5.47us    / 6.9us (slow-clock regime)
//   branchless,  grid  8x256 : 5.8us     / 6.6-6.9us (slow regime)
// Wall time is DVFS-bimodal (~4.6 vs ~6.6-6.9 for identical code); ncu dur
// shows the branchless body is ~25% faster and wider grids shave the
// completion tail. This round: branchless body + 32 CTAs x 64 threads
// (32 SMs x 2 warps -> minimal per-SM L1tex queueing, moderate grid walk).

#define THRESHOLD 0.4f

__global__ void __launch_bounds__(64, 1)
vis_heatmap_kernel(const float* __restrict__ coords,
                   const float* __restrict__ heatmaps,
                   float* __restrict__ out)
{
    int i = blockIdx.x * 64 + threadIdx.x;   // exact fit (2048 = 32*64)

    // Coalesced vectorized coord load: (u, v) NDC
    float2 c = reinterpret_cast<const float2*>(coords)[i];

    // ndc -> pixel via single FMA each; truncate toward zero (.astype(int32))
    int u = (int)__fmaf_rn(c.x, 128.0f, 128.0f);   // (x+1)*0.5*256
    int v = (int)__fmaf_rn(c.y, 128.0f, 128.0f);

    // valid iff 0 <= u < 256 and 0 <= v < 256 (one unsigned compare each)
    bool valid = ((unsigned)u < 256u) & ((unsigned)v < 256u);

    // Clamp and ALWAYS load (branchless; reference also clamps then masks).
    int uc = min(max(u, 0), 255);
    int vc = min(max(v, 0), 255);
    unsigned idx = ((unsigned)i << 16) | ((unsigned)vc << 8) | (unsigned)uc;
    float val = __ldg(&heatmaps[idx]);

    float m = (valid & (val > THRESHOLD)) ? 1.0f : 0.0f;

    // Coalesced vectorized store: broadcast mask to both lanes
    reinterpret_cast<float2*>(out)[i] = make_float2(m, m);
}

extern "C" void kernel_launch(void* const* d_in, const int* in_sizes, int n_in,
                              void* d_out, int out_size)
{
    const float* coords   = (const float*)d_in[0];
    const float* heatmaps = (const float*)d_in[1];
    float* out = (float*)d_out;

    int n = in_sizes[0] / 2;         // B*K = 2048 keypoints
    int blocks = (n + 63) / 64;      // = 32 CTAs x 64 threads
    vis_heatmap_kernel<<<blocks, 64>>>(coords, heatmaps, out);
}

// round 8
// speedup vs baseline: 1.4931x; 1.4931x over previous
#include <cuda_runtime.h>

// VisibilityHeatmap: per (b,k) keypoint, NDC coord -> pixel index, gather ONE
// heatmap value, threshold, broadcast mask to both coord lanes.
//
// coords [B=32,K=64,2] f32, heatmaps [B,K,256,256] f32, out [B,K,2] f32.
// Latency-bound micro-kernel: 2048 independent gathers, ~260KB touched.
//
// Tuning history (ncu kernel dur; harness wall is DVFS-bimodal ~4.6/~6.8us
// for identical code and not kernel-addressable):
//   branchy  8x256 : 7.7-8.2us
//   branchless 64x32 : 5.47us   branchless 8x256 : 5.8us
//   branchless 32x64 : 5.31us   <- shape optimum (32 SMs x 2 warps)
// This round: streaming coord load (.cs) + streaming mask store (.cs);
// gather stays .nc/ldg for L2 residency across graph replays.

#define THRESHOLD 0.4f

__global__ void __launch_bounds__(64, 1)
vis_heatmap_kernel(const float* __restrict__ coords,
                   const float* __restrict__ heatmaps,
                   float* __restrict__ out)
{
    int i = blockIdx.x * 64 + threadIdx.x;   // exact fit (2048 = 32*64)

    // Coalesced vectorized coord load, streaming policy (read-once data)
    float2 c = __ldcs(reinterpret_cast<const float2*>(coords) + i);

    // ndc -> pixel via single FMA each; truncate toward zero (.astype(int32))
    int u = (int)__fmaf_rn(c.x, 128.0f, 128.0f);   // (x+1)*0.5*256
    int v = (int)__fmaf_rn(c.y, 128.0f, 128.0f);

    // valid iff 0 <= u < 256 and 0 <= v < 256 (one unsigned compare each)
    bool valid = ((unsigned)u < 256u) & ((unsigned)v < 256u);

    // Clamp and ALWAYS load (branchless; reference also clamps then masks).
    int uc = min(max(u, 0), 255);
    int vc = min(max(v, 0), 255);
    unsigned idx = ((unsigned)i << 16) | ((unsigned)vc << 8) | (unsigned)uc;
    float val = __ldg(&heatmaps[idx]);   // .nc: keep heatmap lines L2-warm

    float m = (valid & (val > THRESHOLD)) ? 1.0f : 0.0f;

    // Coalesced vectorized store, streaming policy (write-once output)
    __stcs(reinterpret_cast<float2*>(out) + i, make_float2(m, m));
}

extern "C" void kernel_launch(void* const* d_in, const int* in_sizes, int n_in,
                              void* d_out, int out_size)
{
    const float* coords   = (const float*)d_in[0];
    const float* heatmaps = (const float*)d_in[1];
    float* out = (float*)d_out;

    int n = in_sizes[0] / 2;         // B*K = 2048 keypoints
    int blocks = (n + 63) / 64;      // = 32 CTAs x 64 threads
    vis_heatmap_kernel<<<blocks, 64>>>(coords, heatmaps, out);
}